// round 2
// baseline (speedup 1.0000x reference)
#include <cuda_runtime.h>
#include <cstdint>

#define BATCH 4
#define C_IN  64
#define O_OUT 64
#define H_DIM 128
#define W_DIM 128
#define HW    (H_DIM * W_DIM)

#define CH 8            // channels per smem stage
#define NTHREADS 128    // 4 warps: warp = o-group; lanes = 4 hq x 8 wp

typedef unsigned long long ull;

// Pre-scaled input y = x * f(alpha)
__device__ __align__(16) float y_buf[BATCH * C_IN * H_DIM * W_DIM];

__device__ __forceinline__ ull pack2(float lo, float hi) {
    ull r;
    asm("mov.b64 %0, {%1, %2};" : "=l"(r) : "f"(lo), "f"(hi));
    return r;
}
__device__ __forceinline__ void unpack2(ull v, float& lo, float& hi) {
    asm("mov.b64 {%0, %1}, %2;" : "=f"(lo), "=f"(hi) : "l"(v));
}
__device__ __forceinline__ ull fma2(ull a, ull b, ull c) {
    ull d;
    asm("fma.rn.f32x2 %0, %1, %2, %3;" : "=l"(d) : "l"(a), "l"(b), "l"(c));
    return d;
}

// ---------------- Kernel A: y = x * ((a*alpha + b)*alpha + c) ----------------
__global__ __launch_bounds__(256)
void prep_y_kernel(const float4* __restrict__ x4,
                   const float4* __restrict__ a4,
                   const float* __restrict__ pa,
                   const float* __restrict__ pb,
                   const float* __restrict__ pc)
{
    const float ka = *pa, kb = *pb, kc = *pc;
    const int idx = blockIdx.x * 256 + threadIdx.x;   // float4 index
    // total float4 = 4*64*128*128/4 = 1048576; grid sized exactly
    const int e  = idx << 2;
    const int b  = e >> 20;               // / (C_IN*HW) = 2^20
    const int hw4 = (e & (HW - 1)) >> 2;  // alpha float4 index within image

    const float4 xv = x4[idx];
    const float4 av = a4[b * (HW / 4) + hw4];

    float4 yv;
    yv.x = xv.x * ((ka * av.x + kb) * av.x + kc);
    yv.y = xv.y * ((ka * av.y + kb) * av.y + kc);
    yv.z = xv.z * ((ka * av.z + kb) * av.z + kc);
    yv.w = xv.w * ((ka * av.w + kb) * av.w + kc);

    reinterpret_cast<float4*>(y_buf)[idx] = yv;
}

// ---------------- Kernel B: standard 3x3 conv on y ----------------
// Block: 16x16 spatial tile, 16 output channels (4 warps x 4 o each).
// Thread: 4 output rows x 1 w-pair x 4 o.  f32x2 lanes = (w, w+1).
__global__ __launch_bounds__(NTHREADS)
void conv3x3_kernel(const float* __restrict__ wgt,
                    const float* __restrict__ bias,
                    float* __restrict__ out)
{
    __shared__ __align__(16) float ysm[CH][18][20];   // 18 rows halo, 20-col pad
    __shared__ __align__(16) ull   wsm[9][CH][16];    // (w,w) duplicated pairs

    const int bx = blockIdx.x;            // 8 w tiles
    const int by = blockIdx.y;            // 8 h tiles
    const int bz = blockIdx.z;            // batch*4 + o-slice
    const int batch = bz >> 2;
    const int obase = (bz & 3) * 16;

    const int tid = threadIdx.x;
    const int og  = tid >> 5;             // warp = o-group (0..3)
    const int hq  = (tid >> 3) & 3;       // row-quad (0..3)
    const int wp  = tid & 7;              // w-pair   (0..7)

    ull acc[4][4];                        // [row][o] f32x2 over (w,w+1)
    #pragma unroll
    for (int r = 0; r < 4; r++)
        #pragma unroll
        for (int o = 0; o < 4; o++)
            acc[r][o] = 0ull;

    const int gy0 = by * 16 - 1;          // halo origin
    const int gx0 = bx * 16 - 1;

    for (int c0 = 0; c0 < C_IN; c0 += CH) {
        // ---- Stage y tile (CH channels, 18x18 halo) ----
        #pragma unroll 1
        for (int idx = tid; idx < CH * 18 * 18; idx += NTHREADS) {
            const int cc  = idx / 324;
            const int rr  = idx % 324;
            const int row = rr / 18;
            const int col = rr % 18;
            const int gy  = gy0 + row;
            const int gx  = gx0 + col;
            float v = 0.f;
            if (gy >= 0 && gy < H_DIM && gx >= 0 && gx < W_DIM)
                v = y_buf[((batch * C_IN + c0 + cc) * H_DIM + gy) * W_DIM + gx];
            ysm[cc][row][col] = v;
        }
        // ---- Stage weights as duplicated (w,w) pairs: [tap][c][o] ----
        #pragma unroll 1
        for (int idx = tid; idx < 9 * CH * 16; idx += NTHREADS) {
            const int tap = idx / (CH * 16);
            const int rr  = idx % (CH * 16);
            const int cc  = rr / 16;
            const int ol  = rr % 16;
            const float w = wgt[(obase + ol) * (C_IN * 9) + (c0 + cc) * 9 + tap];
            wsm[tap][cc][ol] = pack2(w, w);
        }
        __syncthreads();

        #pragma unroll 1
        for (int cc = 0; cc < CH; cc++) {
            // Load 6 rows x 2 aligned pairs, build the 3 overlapping pair variants
            ull P[6][3];
            #pragma unroll
            for (int r = 0; r < 6; r++) {
                const ull y0 = *reinterpret_cast<const ull*>(&ysm[cc][hq * 4 + r][wp * 2]);
                const ull y1 = *reinterpret_cast<const ull*>(&ysm[cc][hq * 4 + r][wp * 2 + 2]);
                P[r][0] = y0;
                P[r][2] = y1;
                float a0, a1, b0, b1;
                unpack2(y0, a0, a1);
                unpack2(y1, b0, b1);
                P[r][1] = pack2(a1, b0);
            }

            #pragma unroll
            for (int i = 0; i < 3; i++) {
                #pragma unroll
                for (int j = 0; j < 3; j++) {
                    const ull* w2 = &wsm[i * 3 + j][cc][og * 4];
                    const ulonglong2 wa = *reinterpret_cast<const ulonglong2*>(&w2[0]);
                    const ulonglong2 wb = *reinterpret_cast<const ulonglong2*>(&w2[2]);
                    #pragma unroll
                    for (int r = 0; r < 4; r++) {
                        const ull p = P[r + i][j];
                        acc[r][0] = fma2(p, wa.x, acc[r][0]);
                        acc[r][1] = fma2(p, wa.y, acc[r][1]);
                        acc[r][2] = fma2(p, wb.x, acc[r][2]);
                        acc[r][3] = fma2(p, wb.y, acc[r][3]);
                    }
                }
            }
        }
        __syncthreads();
    }

    // ---- Epilogue: add bias, store float2 per (row, o) ----
    const int w0 = bx * 16 + wp * 2;
    const int h0 = by * 16 + hq * 4;
    #pragma unroll
    for (int o = 0; o < 4; o++) {
        const int oc = obase + og * 4 + o;
        const float bv = bias[oc];
        float* op = out + ((size_t)(batch * O_OUT + oc) * H_DIM + h0) * W_DIM + w0;
        #pragma unroll
        for (int r = 0; r < 4; r++) {
            float lo, hi;
            unpack2(acc[r][o], lo, hi);
            *reinterpret_cast<float2*>(op + (size_t)r * W_DIM) =
                make_float2(lo + bv, hi + bv);
        }
    }
}

extern "C" void kernel_launch(void* const* d_in, const int* in_sizes, int n_in,
                              void* d_out, int out_size)
{
    const float* x     = (const float*)d_in[0];  // [4,64,128,128]
    const float* alpha = (const float*)d_in[1];  // [4,1,128,128]
    const float* wgt   = (const float*)d_in[2];  // [64,64,3,3]
    const float* bias  = (const float*)d_in[3];  // [64]
    const float* pa    = (const float*)d_in[4];
    const float* pb    = (const float*)d_in[5];
    const float* pc    = (const float*)d_in[6];
    float* out = (float*)d_out;                  // [4,64,128,128]

    const int n4 = BATCH * C_IN * HW / 4;        // 1048576
    prep_y_kernel<<<n4 / 256, 256>>>(
        (const float4*)x, (const float4*)alpha, pa, pb, pc);

    dim3 grid(W_DIM / 16, H_DIM / 16, BATCH * (O_OUT / 16));  // (8, 8, 16)
    conv3x3_kernel<<<grid, NTHREADS>>>(wgt, bias, out);
}

// round 5
// speedup vs baseline: 1.9390x; 1.9390x over previous
#include <cuda_runtime.h>
#include <cuda_bf16.h>
#include <cstdint>
#include <cstddef>

#define BATCH 4
#define C_IN  64
#define O_OUT 64
#define H_DIM 128
#define W_DIM 128

// ---------------- device scratch ----------------
// y = x*f(alpha), pixel-major [b][h][w][c], bf16 hi/lo planes
__device__ __align__(1024) __nv_bfloat16 g_yhi[BATCH * H_DIM * W_DIM * C_IN];
__device__ __align__(1024) __nv_bfloat16 g_ylo[BATCH * H_DIM * W_DIM * C_IN];
// weights repacked: [tap(9)][spl(2)][o(64)][c(64)] bf16
__device__ __align__(1024) __nv_bfloat16 g_w[18 * 64 * 64];

// ---------------- helpers ----------------
__device__ __forceinline__ uint32_t smem_u32(const void* p) {
    uint32_t a;
    asm("{ .reg .u64 t; cvta.to.shared.u64 t, %1; cvt.u32.u64 %0, t; }"
        : "=r"(a) : "l"(p));
    return a;
}
__device__ __forceinline__ void st128(uint32_t dst, uint4 v) {
    asm volatile("st.shared.v4.b32 [%0], {%1,%2,%3,%4};"
                 :: "r"(dst), "r"(v.x), "r"(v.y), "r"(v.z), "r"(v.w) : "memory");
}
__device__ __forceinline__ void ldsm_x4(uint32_t* r, uint32_t addr) {
    asm volatile("ldmatrix.sync.aligned.m8n8.x4.shared.b16 {%0,%1,%2,%3}, [%4];"
                 : "=r"(r[0]), "=r"(r[1]), "=r"(r[2]), "=r"(r[3]) : "r"(addr));
}
__device__ __forceinline__ void mma16816(float* c, const uint32_t* a, const uint32_t* b) {
    asm volatile(
        "mma.sync.aligned.m16n8k16.row.col.f32.bf16.bf16.f32 "
        "{%0,%1,%2,%3}, {%4,%5,%6,%7}, {%8,%9}, {%0,%1,%2,%3};"
        : "+f"(c[0]), "+f"(c[1]), "+f"(c[2]), "+f"(c[3])
        : "r"(a[0]), "r"(a[1]), "r"(a[2]), "r"(a[3]), "r"(b[0]), "r"(b[1]));
}

// ---------------- K1: y = x*f(alpha), transpose, bf16 hi/lo split ----------------
__global__ __launch_bounds__(256)
void prep_kernel(const float* __restrict__ x, const float* __restrict__ alpha,
                 const float* __restrict__ pa, const float* __restrict__ pb,
                 const float* __restrict__ pc)
{
    __shared__ __align__(16) float fa[128];
    __shared__ __align__(16) float ysm[64][132];
    const int bid = blockIdx.x, b = bid >> 7, h = bid & 127;
    const int tid = threadIdx.x;
    const float ka = *pa, kb = *pb, kc = *pc;

    if (tid < 128) {
        const float av = alpha[(b * 128 + h) * 128 + tid];
        fa[tid] = (ka * av + kb) * av + kc;
    }
    __syncthreads();
    {
        const int c = tid >> 2, seg = (tid & 3) * 32;
        const float4* xr = (const float4*)(x + (((size_t)(b * 64 + c) * 128 + h) * 128 + seg));
        const float4* fr = (const float4*)(fa + seg);
        #pragma unroll
        for (int i = 0; i < 8; i++) {
            const float4 xv = xr[i], fv = fr[i];
            ysm[c][seg + 4 * i + 0] = xv.x * fv.x;
            ysm[c][seg + 4 * i + 1] = xv.y * fv.y;
            ysm[c][seg + 4 * i + 2] = xv.z * fv.z;
            ysm[c][seg + 4 * i + 3] = xv.w * fv.w;
        }
    }
    __syncthreads();
    if (tid < 128) {
        const int w = tid;
        uint32_t hibuf[32], lobuf[32];
        #pragma unroll
        for (int p = 0; p < 32; p++) {
            const float y0 = ysm[2 * p][w], y1 = ysm[2 * p + 1][w];
            const __nv_bfloat16 h0 = __float2bfloat16(y0);
            const __nv_bfloat16 h1 = __float2bfloat16(y1);
            const __nv_bfloat16 l0 = __float2bfloat16(y0 - __bfloat162float(h0));
            const __nv_bfloat16 l1 = __float2bfloat16(y1 - __bfloat162float(h1));
            hibuf[p] = (uint32_t)__bfloat16_as_ushort(h0) |
                       ((uint32_t)__bfloat16_as_ushort(h1) << 16);
            lobuf[p] = (uint32_t)__bfloat16_as_ushort(l0) |
                       ((uint32_t)__bfloat16_as_ushort(l1) << 16);
        }
        uint4* dhi = (uint4*)(g_yhi + ((size_t)((b * 128 + h) * 128 + w)) * 64);
        uint4* dlo = (uint4*)(g_ylo + ((size_t)((b * 128 + h) * 128 + w)) * 64);
        #pragma unroll
        for (int j = 0; j < 8; j++) {
            dhi[j] = make_uint4(hibuf[4*j], hibuf[4*j+1], hibuf[4*j+2], hibuf[4*j+3]);
            dlo[j] = make_uint4(lobuf[4*j], lobuf[4*j+1], lobuf[4*j+2], lobuf[4*j+3]);
        }
    }
}

// ---------------- K2: repack W -> [tap][spl][o][c] bf16 ----------------
__global__ __launch_bounds__(256)
void wprep_kernel(const float* __restrict__ wgt)
{
    const int e = blockIdx.x * 256 + threadIdx.x;   // 144*256 = 36864
    const int o = e / 576, r = e % 576, c = r / 9, tap = r % 9;
    const float v = wgt[e];
    const __nv_bfloat16 hv = __float2bfloat16(v);
    const __nv_bfloat16 lv = __float2bfloat16(v - __bfloat162float(hv));
    g_w[((size_t)(tap * 2 + 0) * 64 + o) * 64 + c] = hv;
    g_w[((size_t)(tap * 2 + 1) * 64 + o) * 64 + c] = lv;
}

// ---------------- K3: conv via mma.sync bf16 ----------------
// CTA = one (b,h) row.  M=128 pixels x N=64 outputs, fp32 reg accumulators.
// A smem: 6 regions (3 h-rows x hi/lo), 130 rows (halo) x 144B stride.
// B smem: 2 tiles (hi/lo) 64 o-rows x 144B stride, refilled per tap.
#define ASTR 144
#define AREG (130 * 144)            // 18720
#define B_OFF (6 * AREG)            // 112320
#define BSTR 144
#define SMEM_TOTAL (B_OFF + 2 * 64 * BSTR)   // 130752

__global__ __launch_bounds__(256, 1)
void conv_kernel(const float* __restrict__ bias, float* __restrict__ out)
{
    extern __shared__ __align__(128) unsigned char smem[];
    const uint32_t sb = smem_u32(smem);
    const int tid = threadIdx.x, lane = tid & 31, wid = tid >> 5;
    const int bid = blockIdx.x, b = bid >> 7, h = bid & 127;
    const int m0 = (wid >> 1) * 32, n0 = (wid & 1) * 32;

    // ---- stage A: 3 h-rows x 2 splits x 128 pixels x 8 x 16B chunks ----
    #pragma unroll 1
    for (int it = 0; it < 24; it++) {
        const int task = tid + it * 256;
        const int ch = task & 7, w = (task >> 3) & 127;
        const int spl = (task >> 10) & 1, hr = task >> 11;
        const int hs = h + hr - 1;
        uint4 v = make_uint4(0u, 0u, 0u, 0u);
        if ((unsigned)hs < 128u) {
            const __nv_bfloat16* pl = spl ? g_ylo : g_yhi;
            v = ((const uint4*)(pl + ((size_t)((b * 128 + hs) * 128 + w)) * 64))[ch];
        }
        st128(sb + (uint32_t)(hr * 2 + spl) * AREG + (uint32_t)(w + 1) * ASTR + ch * 16, v);
    }
    if (tid < 96) {   // zero halo rows 0 and 129 of each region
        const int ch = tid & 7, rr = (tid >> 3) & 1, reg = tid >> 4;
        st128(sb + (uint32_t)reg * AREG + (uint32_t)(rr ? 129 : 0) * ASTR + ch * 16,
              make_uint4(0u, 0u, 0u, 0u));
    }

    float acc[2][4][4] = {};

    // per-lane ldmatrix address components
    const int t8 = lane >> 3, r8 = lane & 7;
    const int a_row  = ((t8 & 1) << 3) + r8;      // tiles 0/1: rows, 2/3: k+8
    const int a_koff = (t8 >> 1) << 3;
    const int b_orow = ((t8 >> 1) << 3) + r8;     // B rows = o; tiles 2/3: o+8
    const int b_koff = (t8 & 1) << 3;             // tiles 1/3: k+8

    #pragma unroll 1
    for (int di = 0; di < 3; di++) {
        const int hs = h + di - 1;
        if ((unsigned)hs >= 128u) continue;
        #pragma unroll 1
        for (int dj = 0; dj < 3; dj++) {
            __syncthreads();    // previous compute done (and iter0: A staged)
            {   // copy B tiles (hi & lo) for this tap: 64B per thread
                const int tap = di * 3 + dj;
                const int spl = tid >> 7, rest = tid & 127;
                const int o = rest >> 1, half = rest & 1;
                const uint4* src = (const uint4*)(
                    g_w + ((size_t)((tap * 2 + spl) * 64 + o)) * 64 + half * 32);
                const uint32_t dst = sb + B_OFF + (uint32_t)spl * (64 * BSTR) +
                                     (uint32_t)o * BSTR + half * 64;
                #pragma unroll
                for (int i = 0; i < 4; i++) st128(dst + i * 16, src[i]);
            }
            __syncthreads();

            #pragma unroll 1
            for (int term = 0; term < 3; term++) {
                const int aspl = (term == 2) ? 1 : 0;   // hi*Whi, hi*Wlo, lo*Whi
                const int wspl = (term == 1) ? 1 : 0;
                const uint32_t abase = sb + (uint32_t)(di * 2 + aspl) * AREG;
                const uint32_t bbase = sb + B_OFF + (uint32_t)wspl * (64 * BSTR);
                #pragma unroll
                for (int k0 = 0; k0 < 64; k0 += 16) {
                    uint32_t a[2][4], bf[2][4];
                    #pragma unroll
                    for (int mi = 0; mi < 2; mi++)
                        ldsm_x4(a[mi],
                            abase + (uint32_t)(m0 + mi * 16 + a_row + dj) * ASTR +
                            (uint32_t)(k0 + a_koff) * 2);
                    #pragma unroll
                    for (int ni = 0; ni < 2; ni++)
                        ldsm_x4(bf[ni],   // non-trans: [o][c] rows give B[k][n] frags
                            bbase + (uint32_t)(n0 + ni * 16 + b_orow) * BSTR +
                            (uint32_t)(k0 + b_koff) * 2);
                    #pragma unroll
                    for (int mi = 0; mi < 2; mi++)
                        #pragma unroll
                        for (int nj = 0; nj < 4; nj++)
                            mma16816(acc[mi][nj], a[mi], &bf[nj >> 1][(nj & 1) * 2]);
                }
            }
        }
    }

    // ---- epilogue ----
    const int orow = lane >> 2, opair = (lane & 3) * 2;
    #pragma unroll
    for (int nj = 0; nj < 4; nj++) {
        const int o = n0 + nj * 8 + opair;
        const float bv0 = bias[o], bv1 = bias[o + 1];
        float* p0 = out + (((size_t)(b * 64 + o)) * 128 + h) * 128;
        float* p1 = p0 + 128 * 128;
        #pragma unroll
        for (int mi = 0; mi < 2; mi++) {
            const int w = m0 + mi * 16 + orow;
            p0[w]     = acc[mi][nj][0] + bv0;
            p1[w]     = acc[mi][nj][1] + bv1;
            p0[w + 8] = acc[mi][nj][2] + bv0;
            p1[w + 8] = acc[mi][nj][3] + bv1;
        }
    }
}

extern "C" void kernel_launch(void* const* d_in, const int* in_sizes, int n_in,
                              void* d_out, int out_size)
{
    const float* x     = (const float*)d_in[0];  // [4,64,128,128]
    const float* alpha = (const float*)d_in[1];  // [4,1,128,128]
    const float* wgt   = (const float*)d_in[2];  // [64,64,3,3]
    const float* bias  = (const float*)d_in[3];  // [64]
    const float* pa    = (const float*)d_in[4];
    const float* pb    = (const float*)d_in[5];
    const float* pc    = (const float*)d_in[6];
    float* out = (float*)d_out;                  // [4,64,128,128]

    cudaFuncSetAttribute(conv_kernel,
                         cudaFuncAttributeMaxDynamicSharedMemorySize, SMEM_TOTAL);

    wprep_kernel<<<144, 256>>>(wgt);
    prep_kernel<<<BATCH * H_DIM, 256>>>(x, alpha, pa, pb, pc);
    conv_kernel<<<BATCH * H_DIM, 256, SMEM_TOTAL>>>(bias, out);
}

// round 6
// speedup vs baseline: 2.6299x; 1.3563x over previous
#include <cuda_runtime.h>
#include <cuda_bf16.h>
#include <cstdint>
#include <cstddef>

#define BATCH 4
#define C_IN  64
#define O_OUT 64
#define H_DIM 128
#define W_DIM 128

// ---------------- device scratch ----------------
__device__ __align__(1024) __nv_bfloat16 g_yhi[BATCH * H_DIM * W_DIM * C_IN];
__device__ __align__(1024) __nv_bfloat16 g_ylo[BATCH * H_DIM * W_DIM * C_IN];
// weights: [tap(9)][spl(2)][o(64)][c(64)] bf16
__device__ __align__(1024) __nv_bfloat16 g_w[18 * 64 * 64];

// ---------------- helpers ----------------
__device__ __forceinline__ uint32_t smem_u32(const void* p) {
    uint32_t a;
    asm("{ .reg .u64 t; cvta.to.shared.u64 t, %1; cvt.u32.u64 %0, t; }"
        : "=r"(a) : "l"(p));
    return a;
}
__device__ __forceinline__ void st128(uint32_t dst, uint4 v) {
    asm volatile("st.shared.v4.b32 [%0], {%1,%2,%3,%4};"
                 :: "r"(dst), "r"(v.x), "r"(v.y), "r"(v.z), "r"(v.w) : "memory");
}
__device__ __forceinline__ void ldsm_x4(uint32_t* r, uint32_t addr) {
    asm volatile("ldmatrix.sync.aligned.m8n8.x4.shared.b16 {%0,%1,%2,%3}, [%4];"
                 : "=r"(r[0]), "=r"(r[1]), "=r"(r[2]), "=r"(r[3]) : "r"(addr));
}
__device__ __forceinline__ void mma16816(float* c, const uint32_t* a, const uint32_t* b) {
    asm volatile(
        "mma.sync.aligned.m16n8k16.row.col.f32.bf16.bf16.f32 "
        "{%0,%1,%2,%3}, {%4,%5,%6,%7}, {%8,%9}, {%0,%1,%2,%3};"
        : "+f"(c[0]), "+f"(c[1]), "+f"(c[2]), "+f"(c[3])
        : "r"(a[0]), "r"(a[1]), "r"(a[2]), "r"(a[3]), "r"(b[0]), "r"(b[1]));
}

// ------- K1: weights repack (blocks 0..143) + y = x*f(alpha) transpose/split -------
__global__ __launch_bounds__(256)
void prep_kernel(const float* __restrict__ x, const float* __restrict__ alpha,
                 const float* __restrict__ wgt,
                 const float* __restrict__ pa, const float* __restrict__ pb,
                 const float* __restrict__ pc)
{
    __shared__ __align__(16) float fa[128];
    __shared__ __align__(16) float ysm[64][132];
    const int bid = blockIdx.x, b = bid >> 7, h = bid & 127;
    const int tid = threadIdx.x;
    const float ka = *pa, kb = *pb, kc = *pc;

    if (bid < 144) {   // folded wprep: 144*256 = 36864 = 64*64*9 elements
        const int e = bid * 256 + tid;
        const int o = e / 576, r = e % 576, c = r / 9, tap = r % 9;
        const float v = wgt[e];
        const __nv_bfloat16 hv = __float2bfloat16(v);
        const __nv_bfloat16 lv = __float2bfloat16(v - __bfloat162float(hv));
        g_w[((size_t)(tap * 2 + 0) * 64 + o) * 64 + c] = hv;
        g_w[((size_t)(tap * 2 + 1) * 64 + o) * 64 + c] = lv;
    }

    if (tid < 128) {
        const float av = alpha[(b * 128 + h) * 128 + tid];
        fa[tid] = (ka * av + kb) * av + kc;
    }
    __syncthreads();
    {
        const int c = tid >> 2, seg = (tid & 3) * 32;
        const float4* xr = (const float4*)(x + (((size_t)(b * 64 + c) * 128 + h) * 128 + seg));
        const float4* fr = (const float4*)(fa + seg);
        #pragma unroll
        for (int i = 0; i < 8; i++) {
            const float4 xv = xr[i], fv = fr[i];
            ysm[c][seg + 4 * i + 0] = xv.x * fv.x;
            ysm[c][seg + 4 * i + 1] = xv.y * fv.y;
            ysm[c][seg + 4 * i + 2] = xv.z * fv.z;
            ysm[c][seg + 4 * i + 3] = xv.w * fv.w;
        }
    }
    __syncthreads();
    if (tid < 128) {
        const int w = tid;
        uint32_t hibuf[32], lobuf[32];
        #pragma unroll
        for (int p = 0; p < 32; p++) {
            const float y0 = ysm[2 * p][w], y1 = ysm[2 * p + 1][w];
            const __nv_bfloat16 h0 = __float2bfloat16(y0);
            const __nv_bfloat16 h1 = __float2bfloat16(y1);
            const __nv_bfloat16 l0 = __float2bfloat16(y0 - __bfloat162float(h0));
            const __nv_bfloat16 l1 = __float2bfloat16(y1 - __bfloat162float(h1));
            hibuf[p] = (uint32_t)__bfloat16_as_ushort(h0) |
                       ((uint32_t)__bfloat16_as_ushort(h1) << 16);
            lobuf[p] = (uint32_t)__bfloat16_as_ushort(l0) |
                       ((uint32_t)__bfloat16_as_ushort(l1) << 16);
        }
        uint4* dhi = (uint4*)(g_yhi + ((size_t)((b * 128 + h) * 128 + w)) * 64);
        uint4* dlo = (uint4*)(g_ylo + ((size_t)((b * 128 + h) * 128 + w)) * 64);
        #pragma unroll
        for (int j = 0; j < 8; j++) {
            dhi[j] = make_uint4(hibuf[4*j], hibuf[4*j+1], hibuf[4*j+2], hibuf[4*j+3]);
            dlo[j] = make_uint4(lobuf[4*j], lobuf[4*j+1], lobuf[4*j+2], lobuf[4*j+3]);
        }
    }
}

// ---------------- K2: conv via mma.sync bf16, di-outer restaging ----------------
// CTA = one (b,h) row. M=128 x N=64, fp32 reg acc.
// Per di: A = 2 regions (hi/lo) of this input row, 130x144B; B = 6 tiles (3dj x hi/lo).
#define ASTR 144
#define AREG (130 * 144)            // 18720
#define B_OFF (2 * AREG)            // 37440
#define BTILE (64 * 144)            // 9216
#define SMEM_TOTAL (B_OFF + 6 * BTILE)   // 92736 -> 2 CTAs/SM

__global__ __launch_bounds__(256, 2)
void conv_kernel(const float* __restrict__ bias, float* __restrict__ out)
{
    extern __shared__ __align__(128) unsigned char smem[];
    const uint32_t sb = smem_u32(smem);
    const int tid = threadIdx.x, lane = tid & 31, wid = tid >> 5;
    const int bid = blockIdx.x, b = bid >> 7, h = bid & 127;
    const int m0 = (wid >> 1) * 32, n0 = (wid & 1) * 32;

    float acc[2][4][4] = {};

    // per-lane ldmatrix address components
    const int t8 = lane >> 3, r8 = lane & 7;
    const int a_row  = ((t8 & 1) << 3) + r8;
    const int a_koff = (t8 >> 1) << 3;
    const int b_orow = ((t8 >> 1) << 3) + r8;
    const int b_koff = (t8 & 1) << 3;

    #pragma unroll 1
    for (int di = 0; di < 3; di++) {
        const int hs = h + di - 1;
        if ((unsigned)hs >= 128u) continue;
        __syncthreads();   // previous di's compute done before overwriting smem

        // ---- stage A: 2 spl x 128 w x 8 chunks = 2048 uint4 ----
        #pragma unroll 1
        for (int it = 0; it < 8; it++) {
            const int task = tid + it * 256;
            const int ch = task & 7, w = (task >> 3) & 127, spl = task >> 10;
            const __nv_bfloat16* pl = spl ? g_ylo : g_yhi;
            const uint4 v =
                ((const uint4*)(pl + ((size_t)((b * 128 + hs) * 128 + w)) * 64))[ch];
            st128(sb + (uint32_t)spl * AREG + (uint32_t)(w + 1) * ASTR + ch * 16, v);
        }
        if (tid < 32) {    // zero halo rows 0 and 129
            const int ch = tid & 7, rr = (tid >> 3) & 1, spl = tid >> 4;
            st128(sb + (uint32_t)spl * AREG + (uint32_t)(rr ? 129 : 0) * ASTR + ch * 16,
                  make_uint4(0u, 0u, 0u, 0u));
        }
        // ---- stage B: 6 tiles (3 dj x hi/lo) x 64 o x 8 chunks = 3072 uint4 ----
        #pragma unroll 1
        for (int it = 0; it < 12; it++) {
            const int task = tid + it * 256;
            const int ch = task & 7, o = (task >> 3) & 63;
            const int spl = (task >> 9) & 1, dj = task >> 10;
            const uint4 v = ((const uint4*)(
                g_w + ((size_t)(((di * 3 + dj) * 2 + spl) * 64 + o)) * 64))[ch];
            st128(sb + B_OFF + (uint32_t)(dj * 2 + spl) * BTILE +
                  (uint32_t)o * ASTR + ch * 16, v);
        }
        __syncthreads();

        // ---- compute: 3 dj x 4 k-steps, frags shared across the 3 split terms ----
        #pragma unroll 1
        for (int dj = 0; dj < 3; dj++) {
            const uint32_t bbh = sb + B_OFF + (uint32_t)(dj * 2) * BTILE;
            const uint32_t bbl = bbh + BTILE;
            #pragma unroll
            for (int k0 = 0; k0 < 64; k0 += 16) {
                uint32_t ahi[2][4], alo[2][4], bhi[2][4], blo[2][4];
                #pragma unroll
                for (int mi = 0; mi < 2; mi++) {
                    const uint32_t arow =
                        (uint32_t)(m0 + mi * 16 + a_row + dj) * ASTR +
                        (uint32_t)(k0 + a_koff) * 2;
                    ldsm_x4(ahi[mi], sb + arow);
                    ldsm_x4(alo[mi], sb + AREG + arow);
                }
                #pragma unroll
                for (int ni = 0; ni < 2; ni++) {
                    const uint32_t brow =
                        (uint32_t)(n0 + ni * 16 + b_orow) * ASTR +
                        (uint32_t)(k0 + b_koff) * 2;
                    ldsm_x4(bhi[ni], bbh + brow);
                    ldsm_x4(blo[ni], bbl + brow);
                }
                #pragma unroll
                for (int mi = 0; mi < 2; mi++)
                    #pragma unroll
                    for (int nj = 0; nj < 4; nj++) {
                        mma16816(acc[mi][nj], ahi[mi], &bhi[nj >> 1][(nj & 1) * 2]);
                        mma16816(acc[mi][nj], ahi[mi], &blo[nj >> 1][(nj & 1) * 2]);
                        mma16816(acc[mi][nj], alo[mi], &bhi[nj >> 1][(nj & 1) * 2]);
                    }
            }
        }
    }

    // ---- epilogue ----
    const int orow = lane >> 2, opair = (lane & 3) * 2;
    #pragma unroll
    for (int nj = 0; nj < 4; nj++) {
        const int o = n0 + nj * 8 + opair;
        const float bv0 = bias[o], bv1 = bias[o + 1];
        float* p0 = out + (((size_t)(b * 64 + o)) * 128 + h) * 128;
        float* p1 = p0 + 128 * 128;
        #pragma unroll
        for (int mi = 0; mi < 2; mi++) {
            const int w = m0 + mi * 16 + orow;
            p0[w]     = acc[mi][nj][0] + bv0;
            p1[w]     = acc[mi][nj][1] + bv1;
            p0[w + 8] = acc[mi][nj][2] + bv0;
            p1[w + 8] = acc[mi][nj][3] + bv1;
        }
    }
}

extern "C" void kernel_launch(void* const* d_in, const int* in_sizes, int n_in,
                              void* d_out, int out_size)
{
    const float* x     = (const float*)d_in[0];  // [4,64,128,128]
    const float* alpha = (const float*)d_in[1];  // [4,1,128,128]
    const float* wgt   = (const float*)d_in[2];  // [64,64,3,3]
    const float* bias  = (const float*)d_in[3];  // [64]
    const float* pa    = (const float*)d_in[4];
    const float* pb    = (const float*)d_in[5];
    const float* pc    = (const float*)d_in[6];
    float* out = (float*)d_out;                  // [4,64,128,128]

    cudaFuncSetAttribute(conv_kernel,
                         cudaFuncAttributeMaxDynamicSharedMemorySize, SMEM_TOTAL);

    prep_kernel<<<BATCH * H_DIM, 256>>>(x, alpha, wgt, pa, pb, pc);
    conv_kernel<<<BATCH * H_DIM, 256, SMEM_TOTAL>>>(bias, out);
}